// round 1
// baseline (speedup 1.0000x reference)
#include <cuda_runtime.h>

#define DD 96
#define HH 320
#define WW 320
#define NVOX (DD*HH*WW)
#define CIN 64
#define COUT 64
#define EPSV 1e-5f
#define SLOPE 0.01f

// Dense coord->row+1 map (0 = empty). Zero-initialized at module load;
// each launch clears exactly the cells it touched, so every graph replay
// starts from a clean grid without a 37.5MB memset.
__device__ int g_grid[NVOX];
// Per-channel sum / sumsq for BN (zeroed at the start of every launch).
__device__ float g_stats[2 * COUT];

__global__ void scatter_kernel(const int* __restrict__ coords, int n) {
    int i = blockIdx.x * blockDim.x + threadIdx.x;
    if (i < 2 * COUT) g_stats[i] = 0.0f;
    if (i >= n) return;
    int z = coords[3 * i + 0];
    int y = coords[3 * i + 1];
    int x = coords[3 * i + 2];
    g_grid[(z * HH + y) * WW + x] = i + 1;
}

__global__ void clear_kernel(const int* __restrict__ coords, int n) {
    int i = blockIdx.x * blockDim.x + threadIdx.x;
    if (i >= n) return;
    int z = coords[3 * i + 0];
    int y = coords[3 * i + 1];
    int x = coords[3 * i + 2];
    g_grid[(z * HH + y) * WW + x] = 0;
}

// 4 voxels per 64-thread block; 16 threads per voxel; each thread owns 4
// contiguous output channels (float4 accumulator + float4 weight loads).
// The two voxels inside a warp read the SAME weight addresses per tap, so
// a warp LDG.128 costs only 2 unique 128B wavefronts.
__global__ void __launch_bounds__(64) conv_kernel(
    const float* __restrict__ feat, const int* __restrict__ coords,
    const float* __restrict__ wgt, float* __restrict__ out, int n)
{
    __shared__ float sfeat[4][CIN];
    __shared__ int   snbr[4][27];

    const int tid   = threadIdx.x;
    const int vbase = blockIdx.x * 4;

    // Phase A: 108 neighbor lookups in parallel.
    for (int idx = tid; idx < 4 * 27; idx += 64) {
        int v = idx / 27, k = idx % 27;
        int i = vbase + v;
        int val = 0;
        if (i < n) {
            int z = coords[3 * i + 0] + k / 9       - 1;
            int y = coords[3 * i + 1] + (k / 3) % 3 - 1;
            int x = coords[3 * i + 2] + k % 3       - 1;
            if (z >= 0 && z < DD && y >= 0 && y < HH && x >= 0 && x < WW)
                val = g_grid[(z * HH + y) * WW + x];
        }
        snbr[v][k] = val - 1;   // -1 => empty / out of bounds / past n
    }
    __syncthreads();

    const int v  = tid >> 4;          // voxel within block (0..3)
    const int c4 = (tid & 15) << 2;   // first of 4 owned output channels
    const int i  = vbase + v;

    float4 acc = make_float4(0.f, 0.f, 0.f, 0.f);

    for (int k = 0; k < 27; k++) {
        int jme = snbr[v][k];
        int jot = snbr[v ^ 1][k];     // partner voxel in same warp
        if (jme < 0 && jot < 0) continue;   // warp-uniform skip (~25 of 27)

        if (jme >= 0)
            *(float4*)&sfeat[v][c4] =
                *(const float4*)&feat[(size_t)jme * CIN + c4];
        __syncwarp();

        if (jme >= 0) {
            const float* wb = wgt + (size_t)k * CIN * COUT + c4;
            #pragma unroll
            for (int cin = 0; cin < CIN; cin += 4) {
                float4 s = *(const float4*)&sfeat[v][cin];
                float4 w;
                w = *(const float4*)(wb + (cin + 0) * COUT);
                acc.x += s.x * w.x; acc.y += s.x * w.y;
                acc.z += s.x * w.z; acc.w += s.x * w.w;
                w = *(const float4*)(wb + (cin + 1) * COUT);
                acc.x += s.y * w.x; acc.y += s.y * w.y;
                acc.z += s.y * w.z; acc.w += s.y * w.w;
                w = *(const float4*)(wb + (cin + 2) * COUT);
                acc.x += s.z * w.x; acc.y += s.z * w.y;
                acc.z += s.z * w.z; acc.w += s.z * w.w;
                w = *(const float4*)(wb + (cin + 3) * COUT);
                acc.x += s.w * w.x; acc.y += s.w * w.y;
                acc.z += s.w * w.z; acc.w += s.w * w.w;
            }
        }
        __syncwarp();   // protect sfeat before next tap overwrites it
    }

    if (i < n)
        *(float4*)&out[(size_t)i * COUT + c4] = acc;
}

__global__ void __launch_bounds__(512) reduce_kernel(
    const float* __restrict__ out, int n)
{
    const int tid = threadIdx.x;
    const int c   = tid & 63;
    const int g   = tid >> 6;   // 0..7 row-groups per block

    float s = 0.f, s2 = 0.f;
    for (int row = blockIdx.x * 8 + g; row < n; row += gridDim.x * 8) {
        float v = out[(size_t)row * COUT + c];
        s  += v;
        s2 += v * v;
    }

    __shared__ float sh[2][512];
    sh[0][tid] = s;
    sh[1][tid] = s2;
    __syncthreads();

    if (tid < 64) {
        #pragma unroll
        for (int gg = 1; gg < 8; gg++) {
            s  += sh[0][tid + gg * 64];
            s2 += sh[1][tid + gg * 64];
        }
        atomicAdd(&g_stats[c],       s);
        atomicAdd(&g_stats[64 + c],  s2);
    }
}

__global__ void __launch_bounds__(256) bn_kernel(
    float4* __restrict__ out, const float* __restrict__ gamma,
    const float* __restrict__ beta, int n4, float invN)
{
    __shared__ float ssc[COUT], sbi[COUT];
    if (threadIdx.x < COUT) {
        float mean = g_stats[threadIdx.x] * invN;
        float var  = g_stats[COUT + threadIdx.x] * invN - mean * mean;
        float sc   = gamma[threadIdx.x] * rsqrtf(var + EPSV);
        ssc[threadIdx.x] = sc;
        sbi[threadIdx.x] = beta[threadIdx.x] - mean * sc;
    }
    __syncthreads();

    int idx = blockIdx.x * blockDim.x + threadIdx.x;
    if (idx >= n4) return;
    int c4 = (idx & 15) << 2;   // 16 float4 per row of 64 channels

    float4 vv = out[idx];
    float r;
    r = vv.x * ssc[c4 + 0] + sbi[c4 + 0]; vv.x = (r >= 0.f) ? r : SLOPE * r;
    r = vv.y * ssc[c4 + 1] + sbi[c4 + 1]; vv.y = (r >= 0.f) ? r : SLOPE * r;
    r = vv.z * ssc[c4 + 2] + sbi[c4 + 2]; vv.z = (r >= 0.f) ? r : SLOPE * r;
    r = vv.w * ssc[c4 + 3] + sbi[c4 + 3]; vv.w = (r >= 0.f) ? r : SLOPE * r;
    out[idx] = vv;
}

extern "C" void kernel_launch(void* const* d_in, const int* in_sizes, int n_in,
                              void* d_out, int out_size)
{
    const float* feat   = (const float*)d_in[0];
    const int*   coords = (const int*)  d_in[1];
    const float* wgt    = (const float*)d_in[2];
    const float* gamma  = (const float*)d_in[3];
    const float* beta   = (const float*)d_in[4];
    float*       out    = (float*)d_out;

    const int n = in_sizes[0] / CIN;

    scatter_kernel<<<(n + 255) / 256, 256>>>(coords, n);
    conv_kernel<<<(n + 3) / 4, 64>>>(feat, coords, wgt, out, n);
    reduce_kernel<<<296, 512>>>(out, n);
    bn_kernel<<<(n * (COUT / 4) + 255) / 256, 256>>>(
        (float4*)out, gamma, beta, n * (COUT / 4), 1.0f / (float)n);
    clear_kernel<<<(n + 255) / 256, 256>>>(coords, n);
}

// round 2
// speedup vs baseline: 1.2146x; 1.2146x over previous
#include <cuda_runtime.h>

#define DD 96
#define HH 320
#define WW 320
#define NVOX (DD*HH*WW)
#define CIN 64
#define COUT 64
#define EPSV 1e-5f
#define SLOPE 0.01f

// Dense coord->row+1 map (0 = empty). Zero-initialized at module load;
// each launch clears exactly the cells it touched so graph replays are clean.
__device__ int g_grid[NVOX];
__device__ float g_stats[2 * COUT];

__global__ void scatter_kernel(const int* __restrict__ coords, int n) {
    int i = blockIdx.x * blockDim.x + threadIdx.x;
    if (i < 2 * COUT) g_stats[i] = 0.0f;
    if (i >= n) return;
    int z = coords[3 * i + 0];
    int y = coords[3 * i + 1];
    int x = coords[3 * i + 2];
    g_grid[(z * HH + y) * WW + x] = i + 1;
}

__global__ void clear_kernel(const int* __restrict__ coords, int n) {
    int i = blockIdx.x * blockDim.x + threadIdx.x;
    if (i >= n) return;
    int z = coords[3 * i + 0];
    int y = coords[3 * i + 1];
    int x = coords[3 * i + 2];
    g_grid[(z * HH + y) * WW + x] = 0;
}

// ---------------------------------------------------------------------------
// Center tap (k=13, always valid): dense GEMM out = feat @ W13.
// 128 rows x 64 cols per 256-thread block. Whole K=64 staged in SMEM.
// Each thread: 8 rows x 4 cols of output (32 fp32 accumulators).
// ---------------------------------------------------------------------------
#define GROWS 128
#define FSTRIDE 68   // padded row stride (17 float4) to kill LDS bank conflicts

__global__ void __launch_bounds__(256) center_gemm_kernel(
    const float* __restrict__ feat, const float* __restrict__ wgt,
    float* __restrict__ out, int n)
{
    __shared__ float sW[CIN * COUT];        // 16 KB  [ci][co]
    __shared__ float sF[GROWS * FSTRIDE];   // 34 KB  [r][ci] padded

    const int tid   = threadIdx.x;
    const int rbase = blockIdx.x * GROWS;
    const float* w13 = wgt + (size_t)13 * CIN * COUT;

    // Stage weights: 4096 floats / 256 threads = 4 float4 each.
    #pragma unroll
    for (int t = 0; t < 4; t++) {
        int e = (tid + t * 256) * 4;
        *(float4*)&sW[e] = *(const float4*)&w13[e];
    }
    // Stage features: 128 rows x 16 float4 = 2048 float4 / 256 threads = 8 each.
    #pragma unroll
    for (int t = 0; t < 8; t++) {
        int e  = tid + t * 256;          // float4 index within tile
        int r  = e >> 4;                 // row 0..127
        int q  = e & 15;                 // float4 within row
        int gr = rbase + r;
        float4 v = (gr < n) ? *(const float4*)&feat[(size_t)gr * CIN + q * 4]
                            : make_float4(0.f, 0.f, 0.f, 0.f);
        *(float4*)&sF[r * FSTRIDE + q * 4] = v;
    }
    __syncthreads();

    const int c4 = (tid & 15) << 2;   // 4 owned output columns
    const int rg = tid >> 4;          // row group 0..15 -> rows rg*8 .. rg*8+7
    const int r0 = rg * 8;

    float4 acc[8];
    #pragma unroll
    for (int r = 0; r < 8; r++) acc[r] = make_float4(0.f, 0.f, 0.f, 0.f);

    #pragma unroll 8
    for (int ci = 0; ci < CIN; ci++) {
        float4 w = *(const float4*)&sW[ci * COUT + c4];
        #pragma unroll
        for (int r = 0; r < 8; r++) {
            float f = sF[(r0 + r) * FSTRIDE + ci];
            acc[r].x += f * w.x; acc[r].y += f * w.y;
            acc[r].z += f * w.z; acc[r].w += f * w.w;
        }
    }

    #pragma unroll
    for (int r = 0; r < 8; r++) {
        int gr = rbase + r0 + r;
        if (gr < n)
            *(float4*)&out[(size_t)gr * COUT + c4] = acc[r];
    }
}

// ---------------------------------------------------------------------------
// Remainder: 26 off-center taps, ~1.5% hit rate each. 4 voxels per 64-thread
// block, 16 threads/voxel owning 4 channels. RMW out only if any tap valid.
// ---------------------------------------------------------------------------
__global__ void __launch_bounds__(64) remainder_kernel(
    const float* __restrict__ feat, const int* __restrict__ coords,
    const float* __restrict__ wgt, float* __restrict__ out, int n)
{
    __shared__ float sfeat[4][CIN];
    __shared__ int   snbr[4][27];

    const int tid   = threadIdx.x;
    const int vbase = blockIdx.x * 4;

    for (int idx = tid; idx < 4 * 27; idx += 64) {
        int v = idx / 27, k = idx % 27;
        int i = vbase + v;
        int val = 0;
        if (i < n && k != 13) {
            int z = coords[3 * i + 0] + k / 9       - 1;
            int y = coords[3 * i + 1] + (k / 3) % 3 - 1;
            int x = coords[3 * i + 2] + k % 3       - 1;
            if (z >= 0 && z < DD && y >= 0 && y < HH && x >= 0 && x < WW)
                val = g_grid[(z * HH + y) * WW + x];
        }
        snbr[v][k] = val - 1;   // -1 => empty / OOB / center / past n
    }
    __syncthreads();

    const int v  = tid >> 4;
    const int c4 = (tid & 15) << 2;
    const int i  = vbase + v;

    float4 acc = make_float4(0.f, 0.f, 0.f, 0.f);
    bool used = false;

    for (int k = 0; k < 27; k++) {
        int jme = snbr[v][k];
        int jot = snbr[v ^ 1][k];
        if (jme < 0 && jot < 0) continue;   // warp-uniform skip (most taps)

        if (jme >= 0)
            *(float4*)&sfeat[v][c4] =
                *(const float4*)&feat[(size_t)jme * CIN + c4];
        __syncwarp();

        if (jme >= 0) {
            used = true;
            const float* wb = wgt + (size_t)k * CIN * COUT + c4;
            #pragma unroll
            for (int cin = 0; cin < CIN; cin += 4) {
                float4 s = *(const float4*)&sfeat[v][cin];
                float4 w;
                w = *(const float4*)(wb + (cin + 0) * COUT);
                acc.x += s.x * w.x; acc.y += s.x * w.y;
                acc.z += s.x * w.z; acc.w += s.x * w.w;
                w = *(const float4*)(wb + (cin + 1) * COUT);
                acc.x += s.y * w.x; acc.y += s.y * w.y;
                acc.z += s.y * w.z; acc.w += s.y * w.w;
                w = *(const float4*)(wb + (cin + 2) * COUT);
                acc.x += s.z * w.x; acc.y += s.z * w.y;
                acc.z += s.z * w.z; acc.w += s.z * w.w;
                w = *(const float4*)(wb + (cin + 3) * COUT);
                acc.x += s.w * w.x; acc.y += s.w * w.y;
                acc.z += s.w * w.z; acc.w += s.w * w.w;
            }
        }
        __syncwarp();
    }

    if (i < n && used) {
        float4 o = *(float4*)&out[(size_t)i * COUT + c4];
        o.x += acc.x; o.y += acc.y; o.z += acc.z; o.w += acc.w;
        *(float4*)&out[(size_t)i * COUT + c4] = o;
    }
}

__global__ void __launch_bounds__(512) reduce_kernel(
    const float* __restrict__ out, int n)
{
    const int tid = threadIdx.x;
    const int c   = tid & 63;
    const int g   = tid >> 6;

    float s = 0.f, s2 = 0.f;
    for (int row = blockIdx.x * 8 + g; row < n; row += gridDim.x * 8) {
        float v = out[(size_t)row * COUT + c];
        s  += v;
        s2 += v * v;
    }

    __shared__ float sh[2][512];
    sh[0][tid] = s;
    sh[1][tid] = s2;
    __syncthreads();

    if (tid < 64) {
        #pragma unroll
        for (int gg = 1; gg < 8; gg++) {
            s  += sh[0][tid + gg * 64];
            s2 += sh[1][tid + gg * 64];
        }
        atomicAdd(&g_stats[c],      s);
        atomicAdd(&g_stats[64 + c], s2);
    }
}

__global__ void __launch_bounds__(256) bn_kernel(
    float4* __restrict__ out, const float* __restrict__ gamma,
    const float* __restrict__ beta, int n4, float invN)
{
    __shared__ float ssc[COUT], sbi[COUT];
    if (threadIdx.x < COUT) {
        float mean = g_stats[threadIdx.x] * invN;
        float var  = g_stats[COUT + threadIdx.x] * invN - mean * mean;
        float sc   = gamma[threadIdx.x] * rsqrtf(var + EPSV);
        ssc[threadIdx.x] = sc;
        sbi[threadIdx.x] = beta[threadIdx.x] - mean * sc;
    }
    __syncthreads();

    int idx = blockIdx.x * blockDim.x + threadIdx.x;
    if (idx >= n4) return;
    int c4 = (idx & 15) << 2;

    float4 vv = out[idx];
    float r;
    r = vv.x * ssc[c4 + 0] + sbi[c4 + 0]; vv.x = (r >= 0.f) ? r : SLOPE * r;
    r = vv.y * ssc[c4 + 1] + sbi[c4 + 1]; vv.y = (r >= 0.f) ? r : SLOPE * r;
    r = vv.z * ssc[c4 + 2] + sbi[c4 + 2]; vv.z = (r >= 0.f) ? r : SLOPE * r;
    r = vv.w * ssc[c4 + 3] + sbi[c4 + 3]; vv.w = (r >= 0.f) ? r : SLOPE * r;
    out[idx] = vv;
}

extern "C" void kernel_launch(void* const* d_in, const int* in_sizes, int n_in,
                              void* d_out, int out_size)
{
    const float* feat   = (const float*)d_in[0];
    const int*   coords = (const int*)  d_in[1];
    const float* wgt    = (const float*)d_in[2];
    const float* gamma  = (const float*)d_in[3];
    const float* beta   = (const float*)d_in[4];
    float*       out    = (float*)d_out;

    const int n = in_sizes[0] / CIN;

    scatter_kernel<<<(n + 255) / 256, 256>>>(coords, n);
    center_gemm_kernel<<<(n + GROWS - 1) / GROWS, 256>>>(feat, wgt, out, n);
    remainder_kernel<<<(n + 3) / 4, 64>>>(feat, coords, wgt, out, n);
    reduce_kernel<<<296, 512>>>(out, n);
    bn_kernel<<<(n * (COUT / 4) + 255) / 256, 256>>>(
        (float4*)out, gamma, beta, n * (COUT / 4), 1.0f / (float)n);
    clear_kernel<<<(n + 255) / 256, 256>>>(coords, n);
}